// round 6
// baseline (speedup 1.0000x reference)
#include <cuda_runtime.h>
#include <cuda_bf16.h>
#include <cuda_fp16.h>
#include <math.h>

// ---------------------------------------------------------------------------
// AlphaFoldLoss fused scalar (single kernel, thread-per-pair disto):
//   out = 0.3*l_disto + 0.01*l_plddt + 0.01*l_exp
// N_RES=768, DISTO_BINS=64, LDDT_BINS=50, CA_IDX=1
// ---------------------------------------------------------------------------

#define N_RES      768
#define DBINS      64
#define LBINS      50
#define NATOMS     37
#define NPAIRS     (N_RES * N_RES)
#define NEXP       (N_RES * NATOMS)

#define NLB         96                    // lddt blocks (8 rows each)
#define ROWS_PER_LB 8
#define NBLK        296                   // total blocks (2/SM target)
#define CHUNK       256                   // pairs per stolen chunk (64KB)
#define NCHUNKS     (NPAIRS / CHUNK)      // 2304
#define DYN_BYTES   (CHUNK * DBINS * 4)   // 65536

// device scratch (allocation-free). Zero-init at load; finalizer re-zeroes.
// g_acc: [0]=disto num, [1]=plddt num, [2]=exp num, [4]=S_pb, [5]=S_ca, [6]=S_ex
__device__ double   g_acc[8];
__device__ unsigned g_tile;   // work-stealing ticket
__device__ unsigned g_done;   // completion counter

__device__ __forceinline__ float softplusf(float z) {
    return fmaxf(z, 0.0f) + log1pf(__expf(-fabsf(z)));
}

__device__ __forceinline__ __half2 h2_ex2(__half2 h) {
    unsigned r, a = *(unsigned*)&h;
    asm("ex2.approx.f16x2 %0, %1;" : "=r"(r) : "r"(a));
    return *(__half2*)&r;
}

__device__ __forceinline__ void calc_bin_w(
    const float* __restrict__ pb, const float* __restrict__ pbm,
    int i, int j, int& bin_o, float& w_o)
{
    float dx = __ldg(&pb[i * 3 + 0]) - __ldg(&pb[j * 3 + 0]);
    float dy = __ldg(&pb[i * 3 + 1]) - __ldg(&pb[j * 3 + 1]);
    float dz = __ldg(&pb[i * 3 + 2]) - __ldg(&pb[j * 3 + 2]);
    float d2 = dx * dx + dy * dy + dz * dz;
    float d  = sqrtf(d2);
    int bin = (int)ceilf((d - 2.3125f) * (1.0f / 0.3125f));
    bin = min(max(bin, 0), 63);
#pragma unroll
    for (int f = 0; f < 2; f++) {
        if (bin < 63) {
            float b = 2.3125f + 0.3125f * (float)bin;
            if (d2 > b * b) bin++;
        }
    }
#pragma unroll
    for (int f = 0; f < 2; f++) {
        if (bin > 0) {
            float b = 2.3125f + 0.3125f * (float)(bin - 1);
            if (d2 <= b * b) bin--;
        }
    }
    bin_o = bin;
    w_o   = __ldg(&pbm[i]) * __ldg(&pbm[j]);
}

__global__ void __launch_bounds__(256)
k_all(const float* __restrict__ logits,        // [768*768*64]
      const float* __restrict__ pb,            // [768*3]
      const float* __restrict__ pbm,           // [768]
      const float* __restrict__ lddt_logits,   // [768*50]
      const float* __restrict__ pred_pos,      // [768*37*3]
      const float* __restrict__ true_pos,      // [768*37*3]
      const float* __restrict__ aa_mask,       // [768*37]
      const float* __restrict__ exp_logits,    // [768*37]
      const float* __restrict__ exists,        // [768*37]
      const float* __restrict__ resolution,    // [1]
      float* __restrict__ out)
{
    extern __shared__ float4 dynbuf[];          // 4096 float4 = 64KB
    const unsigned FULL = 0xffffffffu;
    const int t = threadIdx.x;
    const int lane = t & 31, warp = t >> 5;

    __shared__ float red_a[8], red_b[8], tot2[2];
    __shared__ unsigned s_chunk;

    if (blockIdx.x < NLB) {
        // =================== LDDT + EXP + MASK-SUM PATH ===================
        __shared__ float tp[N_RES * 3];
        __shared__ float pp[N_RES * 3];
        __shared__ float mk[N_RES];

        for (int j = t; j < N_RES; j += 256) {
            int off = (j * NATOMS + 1) * 3;  // CA atom
            tp[j * 3 + 0] = true_pos[off + 0];
            tp[j * 3 + 1] = true_pos[off + 1];
            tp[j * 3 + 2] = true_pos[off + 2];
            pp[j * 3 + 0] = pred_pos[off + 0];
            pp[j * 3 + 1] = pred_pos[off + 1];
            pp[j * 3 + 2] = pred_pos[off + 2];
            mk[j] = aa_mask[j * NATOMS + 1];
        }
        __syncthreads();

        for (int r = 0; r < ROWS_PER_LB; r++) {
            const int i = blockIdx.x * ROWS_PER_LB + r;
            const float tix = tp[i * 3], tiy = tp[i * 3 + 1], tiz = tp[i * 3 + 2];
            const float pix = pp[i * 3], piy = pp[i * 3 + 1], piz = pp[i * 3 + 2];
            const float mi = mk[i];

            float sc = 0.0f, ss = 0.0f;
            for (int j = t; j < N_RES; j += 256) {
                if (j == i) continue;
                float dx = tix - tp[j * 3], dy = tiy - tp[j * 3 + 1],
                      dz = tiz - tp[j * 3 + 2];
                float dt = sqrtf(1e-10f + dx * dx + dy * dy + dz * dz);
                float ex = pix - pp[j * 3], ey = piy - pp[j * 3 + 1],
                      ez = piz - pp[j * 3 + 2];
                float dp = sqrtf(1e-10f + ex * ex + ey * ey + ez * ez);
                float scope = (dt < 15.0f) ? (mi * mk[j]) : 0.0f;
                float l1 = fabsf(dt - dp);
                float score = 0.25f *
                    ((l1 < 0.5f ? 1.0f : 0.0f) + (l1 < 1.0f ? 1.0f : 0.0f) +
                     (l1 < 2.0f ? 1.0f : 0.0f) + (l1 < 4.0f ? 1.0f : 0.0f));
                sc += scope;
                ss += scope * score;
            }
            for (int o = 16; o > 0; o >>= 1) {
                sc += __shfl_xor_sync(FULL, sc, o);
                ss += __shfl_xor_sync(FULL, ss, o);
            }
            if (lane == 0) { red_a[warp] = sc; red_b[warp] = ss; }
            __syncthreads();
            if (t == 0) {
                float a = 0.0f, b = 0.0f;
#pragma unroll
                for (int w = 0; w < 8; w++) { a += red_a[w]; b += red_b[w]; }
                tot2[0] = a; tot2[1] = b;
            }
            __syncthreads();

            if (warp == 0) {
                float score_i = (1e-10f + tot2[1]) / (1e-10f + tot2[0]);
                int bin = (int)floorf(score_i * (float)LBINS);
                bin = min(max(bin, 0), LBINS - 1);
                const float* lg = lddt_logits + i * LBINS;
                float v0 = (lane < LBINS) ? lg[lane] : -1e30f;
                float v1 = (lane + 32 < LBINS) ? lg[lane + 32] : -1e30f;
                float m = fmaxf(v0, v1);
                for (int o = 16; o > 0; o >>= 1)
                    m = fmaxf(m, __shfl_xor_sync(FULL, m, o));
                float s = __expf(v0 - m) + __expf(v1 - m);
                for (int o = 16; o > 0; o >>= 1)
                    s += __shfl_xor_sync(FULL, s, o);
                float lse = m + __logf(s);
                if (lane == 0)
                    atomicAdd(&g_acc[1], (double)(mi * (lse - lg[bin])));
            }
            __syncthreads();
        }

        // exp-resolved loss for this block's 8 rows
        {
            float val = 0.0f;
            const int base = blockIdx.x * ROWS_PER_LB * NATOMS;
            for (int e = t; e < ROWS_PER_LB * NATOMS; e += 256) {
                int idx = base + e;
                float x  = exp_logits[idx];
                float mm = aa_mask[idx];
                float err = mm * softplusf(-x) + (1.0f - mm) * softplusf(x);
                val += exists[idx] * err;
            }
            for (int o = 16; o > 0; o >>= 1)
                val += __shfl_xor_sync(FULL, val, o);
            if (lane == 0) red_a[warp] = val;
            __syncthreads();
            if (t == 0) {
                float bs = 0.0f;
#pragma unroll
                for (int w = 0; w < 8; w++) bs += red_a[w];
                atomicAdd(&g_acc[2], (double)bs);
            }
        }

        // mask sums (block 0 only)
        if (blockIdx.x == 0) {
            if (warp == 0) {
                float s1 = 0.0f;
                for (int j = lane; j < N_RES; j += 32) s1 += pbm[j];
                for (int o = 16; o > 0; o >>= 1)
                    s1 += __shfl_xor_sync(FULL, s1, o);
                if (lane == 0) g_acc[4] = (double)s1;
            } else if (warp == 1) {
                float s2 = 0.0f;
                for (int j = lane; j < N_RES; j += 32)
                    s2 += aa_mask[j * NATOMS + 1];
                for (int o = 16; o > 0; o >>= 1)
                    s2 += __shfl_xor_sync(FULL, s2, o);
                if (lane == 0) g_acc[5] = (double)s2;
            } else if (warp == 2) {
                float s3 = 0.0f;
                for (int j = lane; j < NEXP; j += 32) s3 += exists[j];
                for (int o = 16; o > 0; o >>= 1)
                    s3 += __shfl_xor_sync(FULL, s3, o);
                if (lane == 0) g_acc[6] = (double)s3;
            }
        }
        __syncthreads();
    }

    // =================== DISTOGRAM: thread-per-pair, smem-staged ===========
    {
        const __half2 L2E2 = __float2half2_rn(1.44269504f);
        const float4* lg4 = (const float4*)logits;
        // STS target for this thread's 16 staged float4s:
        //   pair p = k*16 + (t>>4), logical slot s = t&15,
        //   physical col(p,s) = (s + (p&15)) & 15, (p&15) == t>>4
        const int sts_off = (t >> 4) * 16 + (((t & 15) + (t >> 4)) & 15);
        const int rot = t & 15;            // my pair's column rotation

        float acc = 0.0f;
        float4 regs[16];
        int   bin_c = 0;  float w_c = 0.0f;

        if (t == 0) s_chunk = atomicAdd(&g_tile, 1u);
        __syncthreads();
        unsigned c = s_chunk;

        if (c < NCHUNKS) {
            const size_t F = (size_t)c * (CHUNK * 16);
#pragma unroll
            for (int k = 0; k < 16; k++) regs[k] = lg4[F + k * 256 + t];
            const int base = (int)c * CHUNK;
            calc_bin_w(pb, pbm, base / N_RES, base % N_RES + t, bin_c, w_c);
        }

        while (c < NCHUNKS) {
            __syncthreads();                       // buffer free (prev compute done)
#pragma unroll
            for (int k = 0; k < 16; k++) dynbuf[k * 256 + sts_off] = regs[k];
            if (t == 0) s_chunk = atomicAdd(&g_tile, 1u);
            __syncthreads();                       // STS + ticket visible
            const unsigned cn = s_chunk;

            if (cn < NCHUNKS) {                    // prefetch next chunk
                const size_t F = (size_t)cn * (CHUNK * 16);
#pragma unroll
                for (int k = 0; k < 16; k++) regs[k] = lg4[F + k * 256 + t];
            }

            // ---- compute my pair from smem (no cross-lane ops) ----
            const float4* mybuf = dynbuf + t * 16;
            float2 facc = make_float2(0.0f, 0.0f);
#pragma unroll
            for (int s = 0; s < 16; s++) {
                float4 x = mybuf[(s + rot) & 15];
                __half2 h0 = __floats2half2_rn(x.x, x.y);
                __half2 h1 = __floats2half2_rn(x.z, x.w);
                __half2 e  = __hadd2(h2_ex2(__hmul2(h0, L2E2)),
                                     h2_ex2(__hmul2(h1, L2E2)));
                float2 ef = __half22float2(e);
                facc.x += ef.x;
                facc.y += ef.y;
            }
            float lse = __logf(facc.x + facc.y);

            const int fj = bin_c >> 2, comp = bin_c & 3;
            float4 xt = mybuf[(fj + rot) & 15];
            float tgt = (comp == 0) ? xt.x : (comp == 1) ? xt.y
                      : (comp == 2) ? xt.z : xt.w;
            acc += (lse - tgt) * w_c;

            if (cn < NCHUNKS) {                    // next chunk's bin/weight
                const int base = (int)cn * CHUNK;
                calc_bin_w(pb, pbm, base / N_RES, base % N_RES + t, bin_c, w_c);
            }
            c = cn;
        }

        // block reduction -> one double atomic per block
        for (int o = 16; o > 0; o >>= 1)
            acc += __shfl_xor_sync(FULL, acc, o);
        __syncthreads();
        if (lane == 0) red_a[warp] = acc;
        __syncthreads();
        if (t == 0) {
            float bs = 0.0f;
#pragma unroll
            for (int w = 0; w < 8; w++) bs += red_a[w];
            atomicAdd(&g_acc[0], (double)bs);
        }
    }

    // =================== COMPLETION TICKET + FINALIZE ===================
    if (t == 0) {
        __threadfence();
        unsigned old = atomicAdd(&g_done, 1u);
        if (old == gridDim.x - 1) {
            volatile double* ga = g_acc;
            double S_pb = ga[4], S_ca = ga[5], S_ex = ga[6];
            double l_disto = ga[0] / (1e-6 + S_pb * S_pb);
            float res = resolution[0];
            double gate = (res >= 0.1f && res <= 3.0f) ? 1.0 : 0.0;
            double l_plddt = ga[1] / (1e-10 + S_ca) * gate;
            double l_exp   = ga[2] / (1e-8 + S_ex) * gate;
            out[0] = (float)(0.3 * l_disto + 0.01 * l_plddt + 0.01 * l_exp);
            ga[0] = 0.0; ga[1] = 0.0; ga[2] = 0.0;
            __threadfence();
            g_tile = 0u;
            g_done = 0u;
        }
    }
}

// ---------------------------------------------------------------------------
extern "C" void kernel_launch(void* const* d_in, const int* in_sizes, int n_in,
                              void* d_out, int out_size) {
    const float* distogram_logits   = (const float*)d_in[0];
    const float* pseudo_beta        = (const float*)d_in[1];
    const float* pseudo_beta_mask   = (const float*)d_in[2];
    const float* lddt_logits        = (const float*)d_in[3];
    const float* all_atom_pred_pos  = (const float*)d_in[4];
    const float* all_atom_positions = (const float*)d_in[5];
    const float* all_atom_mask      = (const float*)d_in[6];
    const float* exp_resolved_logits= (const float*)d_in[7];
    const float* atom37_atom_exists = (const float*)d_in[8];
    const float* resolution         = (const float*)d_in[9];
    float* out = (float*)d_out;

    cudaFuncSetAttribute(k_all, cudaFuncAttributeMaxDynamicSharedMemorySize,
                         DYN_BYTES);

    k_all<<<NBLK, 256, DYN_BYTES>>>(
        distogram_logits, pseudo_beta, pseudo_beta_mask, lddt_logits,
        all_atom_pred_pos, all_atom_positions, all_atom_mask,
        exp_resolved_logits, atom37_atom_exists, resolution, out);
}